// round 8
// baseline (speedup 1.0000x reference)
#include <cuda_runtime.h>
#include <cstdint>

// Problem constants
#define NNODES 1024
#define BB     8
#define FF     128
#define OO     128
#define DDIR   3
#define NB     (NNODES*BB)      // 8192

// ---------------- scratch (static device memory; no allocations) ----------------
__device__ float g_support[DDIR*NNODES*BB*OO];   // [d][n][b][o]
__device__ float g_supT   [DDIR*BB*OO*NNODES];   // [d*8+b][o][n]  (B as [n][k] for mma row.col)
__device__ float g_agg    [DDIR*NNODES*BB*OO];   // [d][n][b][o] (rows contiguous, 128 wide)
__device__ float g_gi     [DDIR*NNODES*BB*384];  // rows follow agg rows, 384 wide
__device__ float g_ght    [NB*512];              // [n*B+b][ gh_r|gh_z|gh_n|t_pre ]
__device__ float g_x      [NB*FF];               // intermediate x after layer 0
__device__ float g_wT     [2*DDIR*OO*FF];        // W[l,d]^T : [l][d][o][f]
__device__ float g_whcat  [2*512*128];           // [l][n][k]: rows 0..383 Whh, 384..511 Wh^T
__device__ float g_bcat   [2*512];               // [bhh | Bh] per layer

// ======================= helpers =======================
__device__ __forceinline__ uint32_t smem_to_u32(const void* p) {
    uint32_t a;
    asm("{ .reg .u64 t; cvta.to.shared.u64 t, %1; cvt.u32.u64 %0, t; }" : "=r"(a) : "l"(p));
    return a;
}
__device__ __forceinline__ void cp_async16(uint32_t dst, const void* src) {
    asm volatile("cp.async.cg.shared.global [%0], [%1], 16;" :: "r"(dst), "l"(src));
}
__device__ __forceinline__ void cp_commit() {
    asm volatile("cp.async.commit_group;" ::: "memory");
}
template<int N>
__device__ __forceinline__ void cp_wait() {
    asm volatile("cp.async.wait_group %0;" :: "n"(N) : "memory");
}

// split fp32 into tf32 hi + residual lo (exact: lo = v - hi in fp32)
__device__ __forceinline__ void split2(float v, uint32_t& hi, uint32_t& lo) {
    uint32_t u;
    asm("cvt.rna.tf32.f32 %0, %1;" : "=r"(u) : "f"(v));
    hi = u;
    lo = __float_as_uint(v - __uint_as_float(u));
}

__device__ __forceinline__ void mma_tf32(float* c, const uint32_t* a, const uint32_t* b) {
    asm volatile(
        "mma.sync.aligned.m16n8k8.row.col.f32.tf32.tf32.f32 "
        "{%0,%1,%2,%3}, {%4,%5,%6,%7}, {%8,%9}, {%0,%1,%2,%3};"
        : "+f"(c[0]), "+f"(c[1]), "+f"(c[2]), "+f"(c[3])
        : "r"(a[0]), "r"(a[1]), "r"(a[2]), "r"(a[3]), "r"(b[0]), "r"(b[1]));
}

__device__ __forceinline__ float sigmoidf_(float x) {
    return 0.5f * (1.0f + tanhf(0.5f * x));
}

// ---------------------------------------------------------------------------
// Generic tf32 tensor-core GEMM with in-register 3xTF32 (operand-exact).
//   C[z][m][n] = sum_k A[z][m][k] * B[z][n][k]  (+ bias[n])
// Block 256 thr = 8 warps (2 x 4), warp tile 64x32, BM=BN=128, BK=16.
// ---------------------------------------------------------------------------
__global__ void __launch_bounds__(256, 1) mma_gemm_k(
    const float* __restrict__ A, const float* __restrict__ Bm,
    const float* __restrict__ bias, float* __restrict__ C,
    int K, int lda, int ldb, int ldc,
    long aStride, long bStride, int zdiv,
    long cOuter, long cInner, int biasStride)
{
    const int tid   = threadIdx.x;
    const int warp  = tid >> 5;
    const int lane  = tid & 31;
    const int group = lane >> 2;
    const int tig   = lane & 3;
    const int wm    = (warp >> 2) * 64;
    const int wn    = (warp & 3) * 32;
    const int z     = blockIdx.z;

    const long baseA = (long)z*aStride + (long)blockIdx.x*128*lda;
    const long baseB = (long)z*bStride + (long)blockIdx.y*128*ldb;
    const long baseC = (long)(z/zdiv)*cOuter + (long)(z%zdiv)*cInner
                     + (long)blockIdx.x*128*ldc + (long)blockIdx.y*128;

    __shared__ __align__(16) float As[2][128][20];
    __shared__ __align__(16) float Bs[2][128][20];

    float c[4][4][4];
    #pragma unroll
    for (int ma = 0; ma < 4; ma++)
        #pragma unroll
        for (int na = 0; na < 4; na++)
            #pragma unroll
            for (int q = 0; q < 4; q++) c[ma][na][q] = 0.f;

    const int numK = K / 16;
    const int row  = tid >> 2;          // 0..63 (+64 per i)
    const int kq   = (tid & 3) << 2;    // 0,4,8,12

    // -------- preload tile 0 (raw fp32) --------
    #pragma unroll
    for (int i = 0; i < 2; i++) {
        int r = row + i*64;
        *(float4*)&As[0][r][kq] = *(const float4*)&A [baseA + (long)r*lda + kq];
        *(float4*)&Bs[0][r][kq] = *(const float4*)&Bm[baseB + (long)r*ldb + kq];
    }
    __syncthreads();

    for (int kt = 0; kt < numK; kt++) {
        const int  cur = kt & 1;
        const bool has = (kt + 1 < numK);
        float4 pa[2], pb[2];
        if (has) {
            const int k0 = (kt + 1) * 16;
            #pragma unroll
            for (int i = 0; i < 2; i++) {
                int r = row + i*64;
                pa[i] = *(const float4*)&A [baseA + (long)r*lda + k0 + kq];
                pb[i] = *(const float4*)&Bm[baseB + (long)r*ldb + k0 + kq];
            }
        }
        // -------- compute on current buffer (3xTF32 split) --------
        #pragma unroll
        for (int ks = 0; ks < 16; ks += 8) {
            uint32_t bhi[4][2], blo[4][2];
            #pragma unroll
            for (int na = 0; na < 4; na++) {
                int n0 = wn + na*8 + group;
                split2(Bs[cur][n0][ks + tig],     bhi[na][0], blo[na][0]);
                split2(Bs[cur][n0][ks + tig + 4], bhi[na][1], blo[na][1]);
            }
            #pragma unroll
            for (int ma = 0; ma < 4; ma++) {
                int r0 = wm + ma*16 + group;
                uint32_t ahi[4], alo[4];
                split2(As[cur][r0    ][ks + tig],     ahi[0], alo[0]);
                split2(As[cur][r0 + 8][ks + tig],     ahi[1], alo[1]);
                split2(As[cur][r0    ][ks + tig + 4], ahi[2], alo[2]);
                split2(As[cur][r0 + 8][ks + tig + 4], ahi[3], alo[3]);
                #pragma unroll
                for (int na = 0; na < 4; na++) {
                    mma_tf32(c[ma][na], ahi, bhi[na]);
                    mma_tf32(c[ma][na], ahi, blo[na]);
                    mma_tf32(c[ma][na], alo, bhi[na]);
                }
            }
        }
        if (has) {
            const int nxt = cur ^ 1;
            #pragma unroll
            for (int i = 0; i < 2; i++) {
                int r = row + i*64;
                *(float4*)&As[nxt][r][kq] = pa[i];
                *(float4*)&Bs[nxt][r][kq] = pb[i];
            }
            __syncthreads();
        }
    }

    // -------- epilogue: bias + store --------
    const float* bp = bias ? (bias + (long)z*biasStride + blockIdx.y*128) : nullptr;
    #pragma unroll
    for (int ma = 0; ma < 4; ma++) {
        #pragma unroll
        for (int na = 0; na < 4; na++) {
            int gr = wm + ma*16 + group;
            int gc = wn + na*8 + tig*2;
            float b0 = 0.f, b1 = 0.f;
            if (bp) { b0 = bp[gc]; b1 = bp[gc + 1]; }
            long p0 = baseC + (long)gr*ldc + gc;
            float2 v0 = make_float2(c[ma][na][0] + b0, c[ma][na][1] + b1);
            float2 v1 = make_float2(c[ma][na][2] + b0, c[ma][na][3] + b1);
            *(float2*)&C[p0]           = v0;
            *(float2*)&C[p0 + 8*ldc]   = v1;
        }
    }
}

// ---------------------------------------------------------------------------
// Specialized agg GEMM: agg[db][m][o] = adj[db] (1024x1024) @ supT[db]^T (128x1024)
// BM=64, BN=128, BK=16, 4-stage cp.async, warp tile 32x32, 3xTF32 in-register.
// grid (16 mtiles, 24 db), block 256.
// ---------------------------------------------------------------------------
#define AG_STAGES  4
#define AG_ASTRIDE 20
#define AG_ASTAGE  (64*AG_ASTRIDE)     // floats per A stage  (1280)
#define AG_BSTAGE  (128*AG_ASTRIDE)    // floats per B stage  (2560)
#define AG_SMEM_BYTES (AG_STAGES*(AG_ASTAGE + AG_BSTAGE)*4)   // 61440

__device__ __forceinline__ void ag_issue(
    uint32_t asBase, uint32_t bsBase,
    const float* Abase, const float* Bbase,
    int r, int q, int buf, int kt)
{
    cp_async16(asBase + (uint32_t)(buf*AG_ASTAGE + r*AG_ASTRIDE + q*4)*4,
               Abase + (size_t)r*1024 + kt*16 + q*4);
    cp_async16(bsBase + (uint32_t)(buf*AG_BSTAGE + r*AG_ASTRIDE + q*4)*4,
               Bbase + (size_t)r*1024 + kt*16 + q*4);
    cp_async16(bsBase + (uint32_t)(buf*AG_BSTAGE + (r+64)*AG_ASTRIDE + q*4)*4,
               Bbase + (size_t)(r+64)*1024 + kt*16 + q*4);
    cp_commit();
}

__global__ void __launch_bounds__(256, 2)
agg_mma_k(const float* __restrict__ adj, const float* __restrict__ supT,
          float* __restrict__ agg)
{
    extern __shared__ __align__(16) float sm[];
    float* As = sm;                           // [4][64][20]
    float* Bs = sm + AG_STAGES*AG_ASTAGE;     // [4][128][20]
    const uint32_t asBase = smem_to_u32(As);
    const uint32_t bsBase = smem_to_u32(Bs);

    const int tid   = threadIdx.x;
    const int warp  = tid >> 5;
    const int lane  = tid & 31;
    const int group = lane >> 2;
    const int tig   = lane & 3;
    const int wm    = (warp >> 2) * 32;       // 0 or 32
    const int wn    = (warp & 3) * 32;        // 0..96
    const int mt    = blockIdx.x;
    const int db    = blockIdx.y;

    const float* Abase = adj  + (size_t)db*1048576 + (size_t)mt*65536;  // [64 x 1024]
    const float* Bbase = supT + (size_t)db*131072;                      // [128 x 1024]
    const int r = tid >> 2;      // 0..63
    const int q = tid & 3;

    float c[2][4][4];
    #pragma unroll
    for (int ma = 0; ma < 2; ma++)
        #pragma unroll
        for (int na = 0; na < 4; na++)
            #pragma unroll
            for (int j = 0; j < 4; j++) c[ma][na][j] = 0.f;

    // prologue: stages 0..2
    #pragma unroll
    for (int s = 0; s < AG_STAGES - 1; s++)
        ag_issue(asBase, bsBase, Abase, Bbase, r, q, s, s);

    for (int kt = 0; kt < 64; kt++) {
        cp_wait<AG_STAGES - 2>();
        __syncthreads();
        const int buf = kt & 3;
        const float* Asb = As + buf*AG_ASTAGE;
        const float* Bsb = Bs + buf*AG_BSTAGE;
        #pragma unroll
        for (int ks = 0; ks < 16; ks += 8) {
            uint32_t bhi[4][2], blo[4][2];
            #pragma unroll
            for (int na = 0; na < 4; na++) {
                int n0 = wn + na*8 + group;
                split2(Bsb[n0*AG_ASTRIDE + ks + tig],     bhi[na][0], blo[na][0]);
                split2(Bsb[n0*AG_ASTRIDE + ks + tig + 4], bhi[na][1], blo[na][1]);
            }
            #pragma unroll
            for (int ma = 0; ma < 2; ma++) {
                int r0 = wm + ma*16 + group;
                uint32_t ahi[4], alo[4];
                split2(Asb[r0*AG_ASTRIDE + ks + tig],           ahi[0], alo[0]);
                split2(Asb[(r0+8)*AG_ASTRIDE + ks + tig],       ahi[1], alo[1]);
                split2(Asb[r0*AG_ASTRIDE + ks + tig + 4],       ahi[2], alo[2]);
                split2(Asb[(r0+8)*AG_ASTRIDE + ks + tig + 4],   ahi[3], alo[3]);
                #pragma unroll
                for (int na = 0; na < 4; na++) {
                    mma_tf32(c[ma][na], ahi, bhi[na]);
                    mma_tf32(c[ma][na], ahi, blo[na]);
                    mma_tf32(c[ma][na], alo, bhi[na]);
                }
            }
        }
        if (kt + AG_STAGES - 1 < 64)
            ag_issue(asBase, bsBase, Abase, Bbase, r, q, (kt + AG_STAGES - 1) & 3,
                     kt + AG_STAGES - 1);
    }

    // epilogue: agg[d][n][b][o], n = mt*64 + wm + ma*16 + group (+8), o = wn + na*8 + tig*2
    const int d  = db >> 3;
    const int bb = db & 7;
    #pragma unroll
    for (int ma = 0; ma < 2; ma++) {
        #pragma unroll
        for (int na = 0; na < 4; na++) {
            int n0 = mt*64 + wm + ma*16 + group;
            int o  = wn + na*8 + tig*2;
            size_t base = ((size_t)(d*1024 + n0)*8 + bb)*128 + o;
            *(float2*)&agg[base]        = make_float2(c[ma][na][0], c[ma][na][1]);
            *(float2*)&agg[base + 8192] = make_float2(c[ma][na][2], c[ma][na][3]);
        }
    }
}

// ---------------- support transpose: [d][n][b][o] -> [db][o][n] (raw fp32) ----------------
__global__ void transpose_support(const float* __restrict__ sup, float* __restrict__ supT)
{
    __shared__ float t[32][33];
    int db = blockIdx.z;
    int n0 = blockIdx.x * 32, o0 = blockIdx.y * 32;
    int d = db >> 3, b = db & 7;
    int tx = threadIdx.x, ty = threadIdx.y;   // 32 x 8
    #pragma unroll
    for (int j = 0; j < 4; j++) {
        int n = n0 + ty + j*8;
        t[ty + j*8][tx] = sup[((size_t)(d*1024 + n)*8 + b)*128 + o0 + tx];
    }
    __syncthreads();
    #pragma unroll
    for (int j = 0; j < 4; j++) {
        int o = o0 + ty + j*8;
        supT[((size_t)db*128 + o)*1024 + n0 + tx] = t[tx][ty + j*8];
    }
}

// ---------------- one-time weight prep: transposes + concat ----------------
__global__ void prep_weights(const float* __restrict__ W,   const float* __restrict__ Whh,
                             const float* __restrict__ Wh,  const float* __restrict__ bhh,
                             const float* __restrict__ Bh,
                             float* __restrict__ wT, float* __restrict__ whcat,
                             float* __restrict__ bcat)
{
    int idx = blockIdx.x*blockDim.x + threadIdx.x;   // < 131072
    if (idx < 2*DDIR*128*128) {                      // wT[l][d][o][f] = W[l][d][f][o]
        int ld = idx / 16384;                        // l*3+d
        int rem = idx & 16383;
        int o = rem >> 7, f = rem & 127;
        wT[idx] = W[((long)ld*128 + f)*128 + o];
    }
    if (idx < 2*512*128) {                           // whcat[l][n][k]
        int l = idx >> 16;
        int rem = idx & 65535;
        int n = rem >> 7, k = rem & 127;
        whcat[idx] = (n < 384) ? Whh[((long)l*384 + n)*128 + k]
                               : Wh[((long)l*128 + k)*128 + (n - 384)];
    }
    if (idx < 2*512) {
        int l = idx >> 9, j = idx & 511;
        bcat[idx] = (j < 384) ? bhh[l*384 + j] : Bh[l*128 + (j-384)];
    }
}

// ---------------- fused GRU gates + d-sum + relu + highway ----------------
__global__ void gru_highway(const float* __restrict__ xin, const float* __restrict__ ght,
                            const float* __restrict__ gi, float* __restrict__ xout)
{
    int idx = blockIdx.x*blockDim.x + threadIdx.x;
    int o = idx & 127;
    int r = idx >> 7;
    float h = xin[idx];
    const float* g = ght + (long)r*512;
    float ghr = g[o], ghz = g[128+o], ghn = g[256+o];
    float t = fmaxf(g[384+o], 0.0f);
    float acc = 0.0f;
    #pragma unroll
    for (int d = 0; d < 3; d++) {
        const float* gp = gi + ((long)(d*8192 + r))*384;
        float rr = sigmoidf_(gp[o]       + ghr);
        float zz = sigmoidf_(gp[128 + o] + ghz);
        float nn = tanhf    (gp[256 + o] + rr*ghn);
        acc += (1.0f - zz)*nn + zz*h;
    }
    float outv = fmaxf(acc, 0.0f);
    xout[idx] = outv*t + h*(1.0f - t);
}

// ---------------------------------------------------------------------------
extern "C" void kernel_launch(void* const* d_in, const int* in_sizes, int n_in,
                              void* d_out, int out_size)
{
    const float* inputs = (const float*)d_in[0];
    const float* adj    = (const float*)d_in[1];
    const float* W      = (const float*)d_in[2];
    const float* Bc     = (const float*)d_in[3];
    const float* Wh     = (const float*)d_in[4];
    const float* Bh     = (const float*)d_in[5];
    const float* Wih    = (const float*)d_in[6];
    const float* Whh    = (const float*)d_in[7];
    const float* bih    = (const float*)d_in[8];
    const float* bhh    = (const float*)d_in[9];
    float* out = (float*)d_out;
    (void)in_sizes; (void)n_in; (void)out_size;

    float *support, *supT, *agg, *gi, *ght, *xmid, *wT, *whcat, *bcat;
    cudaGetSymbolAddress((void**)&support, g_support);
    cudaGetSymbolAddress((void**)&supT,    g_supT);
    cudaGetSymbolAddress((void**)&agg,     g_agg);
    cudaGetSymbolAddress((void**)&gi,      g_gi);
    cudaGetSymbolAddress((void**)&ght,     g_ght);
    cudaGetSymbolAddress((void**)&xmid,    g_x);
    cudaGetSymbolAddress((void**)&wT,      g_wT);
    cudaGetSymbolAddress((void**)&whcat,   g_whcat);
    cudaGetSymbolAddress((void**)&bcat,    g_bcat);

    cudaFuncSetAttribute(agg_mma_k, cudaFuncAttributeMaxDynamicSharedMemorySize,
                         AG_SMEM_BYTES);

    prep_weights<<<512, 256>>>(W, Whh, Wh, bhh, Bh, wT, whcat, bcat);

    for (int l = 0; l < 2; l++) {
        const float* xi = (l == 0) ? inputs : xmid;
        float*       xo = (l == 1) ? out    : xmid;

        // support[d][nb][o] = x @ W[l,d]^T' + Bc[l,d]   (z = d)
        mma_gemm_k<<<dim3(64,1,3), 256>>>(
            xi, wT + (long)l*DDIR*16384, Bc + l*DDIR*128, support,
            128, 128, 128, 128,
            /*aStride*/0L, /*bStride*/16384L, /*zdiv*/1,
            /*cOuter*/(long)NNODES*BB*OO, /*cInner*/0L, /*biasStride*/128);

        // supT[db][o][n] = support[d][:,b,:]^T
        transpose_support<<<dim3(32,4,24), dim3(32,8)>>>(support, supT);

        // agg[d][m][b][o] = adj[d,b] @ support  (specialized cp.async kernel)
        agg_mma_k<<<dim3(16,24), 256, AG_SMEM_BYTES>>>(adj, supT, agg);

        // gi = agg_flat @ Wih[l]^T + bih   (Wih natively [384][128] = B[n][k])
        mma_gemm_k<<<dim3(192,3,1), 256>>>(
            agg, Wih + (long)l*384*128, bih + l*384, gi,
            128, 128, 128, 384,
            0L, 0L, 1, 0L, 0L, 0);

        // ght = x @ [Whh | Wh^T]^T + [bhh | Bh]
        mma_gemm_k<<<dim3(64,4,1), 256>>>(
            xi, whcat + (long)l*512*128, bcat + l*512, ght,
            128, 128, 128, 512,
            0L, 0L, 1, 0L, 0L, 0);

        gru_highway<<<4096, 256>>>(xi, ght, gi, xo);
    }
}

// round 11
// speedup vs baseline: 1.0651x; 1.0651x over previous
#include <cuda_runtime.h>
#include <cstdint>

// Problem constants
#define NNODES 1024
#define BB     8
#define FF     128
#define OO     128
#define DDIR   3
#define NB     (NNODES*BB)      // 8192

// ---------------- scratch (static device memory; no allocations) ----------------
__device__ float g_support[DDIR*NNODES*BB*OO];   // [d][n][b][o]
__device__ float g_supT   [DDIR*BB*OO*NNODES];   // [d*8+b][o][n]  (tf32-rounded)
__device__ float g_agg    [DDIR*NNODES*BB*OO];   // [d][n][b][o]
__device__ float g_gi     [DDIR*NNODES*BB*384];
__device__ float g_ght    [NB*512];              // [n*B+b][ gh_r|gh_z|gh_n|t_pre ]
__device__ float g_x      [NB*FF];               // intermediate x after layer 0
__device__ float g_wT     [2*DDIR*OO*FF];        // W[l,d]^T : [l][d][o][f] (raw)
__device__ float g_whcat  [2*512*128];           // [l][n][k]: Whh | Wh^T   (raw)
__device__ float g_wihr   [2*384*128];           // Wih, tf32-rounded (for 1x gi)
__device__ float g_bcat   [2*512];               // [bhh | Bh] per layer

// ======================= helpers =======================
__device__ __forceinline__ uint32_t smem_to_u32(const void* p) {
    uint32_t a;
    asm("{ .reg .u64 t; cvta.to.shared.u64 t, %1; cvt.u32.u64 %0, t; }" : "=r"(a) : "l"(p));
    return a;
}
__device__ __forceinline__ void cp_async16(uint32_t dst, const void* src) {
    asm volatile("cp.async.cg.shared.global [%0], [%1], 16;" :: "r"(dst), "l"(src));
}
__device__ __forceinline__ void cp_commit() {
    asm volatile("cp.async.commit_group;" ::: "memory");
}
template<int N>
__device__ __forceinline__ void cp_wait() {
    asm volatile("cp.async.wait_group %0;" :: "n"(N) : "memory");
}

// fp32 -> tf32 round-to-nearest, raw bits
__device__ __forceinline__ uint32_t tf32b(float v) {
    uint32_t u;
    asm("cvt.rna.tf32.f32 %0, %1;" : "=r"(u) : "f"(v));
    return u;
}
__device__ __forceinline__ float tf32f(float v) { return __uint_as_float(tf32b(v)); }

// split fp32 into tf32 hi + residual lo (exact)
__device__ __forceinline__ void split2(float v, uint32_t& hi, uint32_t& lo) {
    hi = tf32b(v);
    lo = __float_as_uint(v - __uint_as_float(hi));
}

__device__ __forceinline__ void mma_tf32(float* c, const uint32_t* a, const uint32_t* b) {
    asm volatile(
        "mma.sync.aligned.m16n8k8.row.col.f32.tf32.tf32.f32 "
        "{%0,%1,%2,%3}, {%4,%5,%6,%7}, {%8,%9}, {%0,%1,%2,%3};"
        : "+f"(c[0]), "+f"(c[1]), "+f"(c[2]), "+f"(c[3])
        : "r"(a[0]), "r"(a[1]), "r"(a[2]), "r"(a[3]), "r"(b[0]), "r"(b[1]));
}

__device__ __forceinline__ float sigmoidf_(float x) {
    return 0.5f * (1.0f + tanhf(0.5f * x));
}

// ---------------------------------------------------------------------------
// 3x (operand-exact) generic GEMM — VERBATIM R8 body, __launch_bounds__(256,1).
//   C[z][m][n] = sum_k A[z][m][k] * B[z][n][k]  (+ bias[n])
// ---------------------------------------------------------------------------
__global__ void __launch_bounds__(256, 1) mma_gemm_3x(
    const float* __restrict__ A, const float* __restrict__ Bm,
    const float* __restrict__ bias, float* __restrict__ C,
    int K, int lda, int ldb, int ldc,
    long aStride, long bStride, int zdiv,
    long cOuter, long cInner, int biasStride)
{
    const int tid   = threadIdx.x;
    const int warp  = tid >> 5;
    const int lane  = tid & 31;
    const int group = lane >> 2;
    const int tig   = lane & 3;
    const int wm    = (warp >> 2) * 64;
    const int wn    = (warp & 3) * 32;
    const int z     = blockIdx.z;

    const long baseA = (long)z*aStride + (long)blockIdx.x*128*lda;
    const long baseB = (long)z*bStride + (long)blockIdx.y*128*ldb;
    const long baseC = (long)(z/zdiv)*cOuter + (long)(z%zdiv)*cInner
                     + (long)blockIdx.x*128*ldc + (long)blockIdx.y*128;

    __shared__ __align__(16) float As[2][128][20];
    __shared__ __align__(16) float Bs[2][128][20];

    float c[4][4][4];
    #pragma unroll
    for (int ma = 0; ma < 4; ma++)
        #pragma unroll
        for (int na = 0; na < 4; na++)
            #pragma unroll
            for (int q = 0; q < 4; q++) c[ma][na][q] = 0.f;

    const int numK = K / 16;
    const int row  = tid >> 2;
    const int kq   = (tid & 3) << 2;

    #pragma unroll
    for (int i = 0; i < 2; i++) {
        int r = row + i*64;
        *(float4*)&As[0][r][kq] = *(const float4*)&A [baseA + (long)r*lda + kq];
        *(float4*)&Bs[0][r][kq] = *(const float4*)&Bm[baseB + (long)r*ldb + kq];
    }
    __syncthreads();

    for (int kt = 0; kt < numK; kt++) {
        const int  cur = kt & 1;
        const bool has = (kt + 1 < numK);
        float4 pa[2], pb[2];
        if (has) {
            const int k0 = (kt + 1) * 16;
            #pragma unroll
            for (int i = 0; i < 2; i++) {
                int r = row + i*64;
                pa[i] = *(const float4*)&A [baseA + (long)r*lda + k0 + kq];
                pb[i] = *(const float4*)&Bm[baseB + (long)r*ldb + k0 + kq];
            }
        }
        #pragma unroll
        for (int ks = 0; ks < 16; ks += 8) {
            uint32_t bhi[4][2], blo[4][2];
            #pragma unroll
            for (int na = 0; na < 4; na++) {
                int n0 = wn + na*8 + group;
                split2(Bs[cur][n0][ks + tig],     bhi[na][0], blo[na][0]);
                split2(Bs[cur][n0][ks + tig + 4], bhi[na][1], blo[na][1]);
            }
            #pragma unroll
            for (int ma = 0; ma < 4; ma++) {
                int r0 = wm + ma*16 + group;
                uint32_t ahi[4], alo[4];
                split2(As[cur][r0    ][ks + tig],     ahi[0], alo[0]);
                split2(As[cur][r0 + 8][ks + tig],     ahi[1], alo[1]);
                split2(As[cur][r0    ][ks + tig + 4], ahi[2], alo[2]);
                split2(As[cur][r0 + 8][ks + tig + 4], ahi[3], alo[3]);
                #pragma unroll
                for (int na = 0; na < 4; na++) {
                    mma_tf32(c[ma][na], ahi, bhi[na]);
                    mma_tf32(c[ma][na], ahi, blo[na]);
                    mma_tf32(c[ma][na], alo, bhi[na]);
                }
            }
        }
        if (has) {
            const int nxt = cur ^ 1;
            #pragma unroll
            for (int i = 0; i < 2; i++) {
                int r = row + i*64;
                *(float4*)&As[nxt][r][kq] = pa[i];
                *(float4*)&Bs[nxt][r][kq] = pb[i];
            }
            __syncthreads();
        }
    }

    const float* bp = bias ? (bias + (long)z*biasStride + blockIdx.y*128) : nullptr;
    #pragma unroll
    for (int ma = 0; ma < 4; ma++) {
        #pragma unroll
        for (int na = 0; na < 4; na++) {
            int gr = wm + ma*16 + group;
            int gc = wn + na*8 + tig*2;
            float b0 = 0.f, b1 = 0.f;
            if (bp) { b0 = bp[gc]; b1 = bp[gc + 1]; }
            long p0 = baseC + (long)gr*ldc + gc;
            *(float2*)&C[p0]         = make_float2(c[ma][na][0] + b0, c[ma][na][1] + b1);
            *(float2*)&C[p0 + 8*ldc] = make_float2(c[ma][na][2] + b0, c[ma][na][3] + b1);
        }
    }
}

// ---------------------------------------------------------------------------
// 1x generic GEMM — B must be PRE-ROUNDED to tf32; A rounded at fragment load.
// Same skeleton, __launch_bounds__(256,2) (R7-proven config for 1x).
// ---------------------------------------------------------------------------
__global__ void __launch_bounds__(256, 2) mma_gemm_1x(
    const float* __restrict__ A, const float* __restrict__ Bm,
    const float* __restrict__ bias, float* __restrict__ C,
    int K, int lda, int ldb, int ldc,
    long aStride, long bStride, int zdiv,
    long cOuter, long cInner, int biasStride)
{
    const int tid   = threadIdx.x;
    const int warp  = tid >> 5;
    const int lane  = tid & 31;
    const int group = lane >> 2;
    const int tig   = lane & 3;
    const int wm    = (warp >> 2) * 64;
    const int wn    = (warp & 3) * 32;
    const int z     = blockIdx.z;

    const long baseA = (long)z*aStride + (long)blockIdx.x*128*lda;
    const long baseB = (long)z*bStride + (long)blockIdx.y*128*ldb;
    const long baseC = (long)(z/zdiv)*cOuter + (long)(z%zdiv)*cInner
                     + (long)blockIdx.x*128*ldc + (long)blockIdx.y*128;

    __shared__ __align__(16) float As[2][128][20];
    __shared__ __align__(16) float Bs[2][128][20];

    float c[4][4][4];
    #pragma unroll
    for (int ma = 0; ma < 4; ma++)
        #pragma unroll
        for (int na = 0; na < 4; na++)
            #pragma unroll
            for (int q = 0; q < 4; q++) c[ma][na][q] = 0.f;

    const int numK = K / 16;
    const int row  = tid >> 2;
    const int kq   = (tid & 3) << 2;

    #pragma unroll
    for (int i = 0; i < 2; i++) {
        int r = row + i*64;
        *(float4*)&As[0][r][kq] = *(const float4*)&A [baseA + (long)r*lda + kq];
        *(float4*)&Bs[0][r][kq] = *(const float4*)&Bm[baseB + (long)r*ldb + kq];
    }
    __syncthreads();

    for (int kt = 0; kt < numK; kt++) {
        const int  cur = kt & 1;
        const bool has = (kt + 1 < numK);
        float4 pa[2], pb[2];
        if (has) {
            const int k0 = (kt + 1) * 16;
            #pragma unroll
            for (int i = 0; i < 2; i++) {
                int r = row + i*64;
                pa[i] = *(const float4*)&A [baseA + (long)r*lda + k0 + kq];
                pb[i] = *(const float4*)&Bm[baseB + (long)r*ldb + k0 + kq];
            }
        }
        #pragma unroll
        for (int ks = 0; ks < 16; ks += 8) {
            uint32_t b[4][2];
            #pragma unroll
            for (int na = 0; na < 4; na++) {
                int n0 = wn + na*8 + group;
                b[na][0] = __float_as_uint(Bs[cur][n0][ks + tig]);      // pre-rounded
                b[na][1] = __float_as_uint(Bs[cur][n0][ks + tig + 4]);
            }
            #pragma unroll
            for (int ma = 0; ma < 4; ma++) {
                int r0 = wm + ma*16 + group;
                uint32_t a[4];
                a[0] = tf32b(As[cur][r0    ][ks + tig]);
                a[1] = tf32b(As[cur][r0 + 8][ks + tig]);
                a[2] = tf32b(As[cur][r0    ][ks + tig + 4]);
                a[3] = tf32b(As[cur][r0 + 8][ks + tig + 4]);
                #pragma unroll
                for (int na = 0; na < 4; na++)
                    mma_tf32(c[ma][na], a, b[na]);
            }
        }
        if (has) {
            const int nxt = cur ^ 1;
            #pragma unroll
            for (int i = 0; i < 2; i++) {
                int r = row + i*64;
                *(float4*)&As[nxt][r][kq] = pa[i];
                *(float4*)&Bs[nxt][r][kq] = pb[i];
            }
            __syncthreads();
        }
    }

    const float* bp = bias ? (bias + (long)z*biasStride + blockIdx.y*128) : nullptr;
    #pragma unroll
    for (int ma = 0; ma < 4; ma++) {
        #pragma unroll
        for (int na = 0; na < 4; na++) {
            int gr = wm + ma*16 + group;
            int gc = wn + na*8 + tig*2;
            float b0 = 0.f, b1 = 0.f;
            if (bp) { b0 = bp[gc]; b1 = bp[gc + 1]; }
            long p0 = baseC + (long)gr*ldc + gc;
            *(float2*)&C[p0]         = make_float2(c[ma][na][0] + b0, c[ma][na][1] + b1);
            *(float2*)&C[p0 + 8*ldc] = make_float2(c[ma][na][2] + b0, c[ma][na][3] + b1);
        }
    }
}

// ---------------------------------------------------------------------------
// Specialized agg GEMM (1x tf32): agg[db] = adj[db] (1024x1024) @ supT[db]^T
// BM=64, BN=128, BK=16, 4-stage cp.async, warp tile 32x32.  (structure = R8)
// ---------------------------------------------------------------------------
#define AG_STAGES  4
#define AG_ASTRIDE 20
#define AG_ASTAGE  (64*AG_ASTRIDE)
#define AG_BSTAGE  (128*AG_ASTRIDE)
#define AG_SMEM_BYTES (AG_STAGES*(AG_ASTAGE + AG_BSTAGE)*4)   // 61440

__device__ __forceinline__ void ag_issue(
    uint32_t asBase, uint32_t bsBase,
    const float* Abase, const float* Bbase,
    int r, int q, int buf, int kt)
{
    cp_async16(asBase + (uint32_t)(buf*AG_ASTAGE + r*AG_ASTRIDE + q*4)*4,
               Abase + (size_t)r*1024 + kt*16 + q*4);
    cp_async16(bsBase + (uint32_t)(buf*AG_BSTAGE + r*AG_ASTRIDE + q*4)*4,
               Bbase + (size_t)r*1024 + kt*16 + q*4);
    cp_async16(bsBase + (uint32_t)(buf*AG_BSTAGE + (r+64)*AG_ASTRIDE + q*4)*4,
               Bbase + (size_t)(r+64)*1024 + kt*16 + q*4);
    cp_commit();
}

__global__ void __launch_bounds__(256, 2)
agg_mma_k(const float* __restrict__ adj, const float* __restrict__ supT,
          float* __restrict__ agg)
{
    extern __shared__ __align__(16) float sm[];
    float* As = sm;
    float* Bs = sm + AG_STAGES*AG_ASTAGE;
    const uint32_t asBase = smem_to_u32(As);
    const uint32_t bsBase = smem_to_u32(Bs);

    const int tid   = threadIdx.x;
    const int warp  = tid >> 5;
    const int lane  = tid & 31;
    const int group = lane >> 2;
    const int tig   = lane & 3;
    const int wm    = (warp >> 2) * 32;
    const int wn    = (warp & 3) * 32;
    const int mt    = blockIdx.x;
    const int db    = blockIdx.y;

    const float* Abase = adj  + (size_t)db*1048576 + (size_t)mt*65536;
    const float* Bbase = supT + (size_t)db*131072;
    const int r = tid >> 2;
    const int q = tid & 3;

    float c[2][4][4];
    #pragma unroll
    for (int ma = 0; ma < 2; ma++)
        #pragma unroll
        for (int na = 0; na < 4; na++)
            #pragma unroll
            for (int j = 0; j < 4; j++) c[ma][na][j] = 0.f;

    #pragma unroll
    for (int s = 0; s < AG_STAGES - 1; s++)
        ag_issue(asBase, bsBase, Abase, Bbase, r, q, s, s);

    for (int kt = 0; kt < 64; kt++) {
        cp_wait<AG_STAGES - 2>();
        __syncthreads();
        const int buf = kt & 3;
        const float* Asb = As + buf*AG_ASTAGE;
        const float* Bsb = Bs + buf*AG_BSTAGE;
        #pragma unroll
        for (int ks = 0; ks < 16; ks += 8) {
            uint32_t b[4][2];
            #pragma unroll
            for (int na = 0; na < 4; na++) {
                int n0 = wn + na*8 + group;
                b[na][0] = __float_as_uint(Bsb[n0*AG_ASTRIDE + ks + tig]);
                b[na][1] = __float_as_uint(Bsb[n0*AG_ASTRIDE + ks + tig + 4]);
            }
            #pragma unroll
            for (int ma = 0; ma < 2; ma++) {
                int r0 = wm + ma*16 + group;
                uint32_t a[4];
                a[0] = tf32b(Asb[r0*AG_ASTRIDE + ks + tig]);
                a[1] = tf32b(Asb[(r0+8)*AG_ASTRIDE + ks + tig]);
                a[2] = tf32b(Asb[r0*AG_ASTRIDE + ks + tig + 4]);
                a[3] = tf32b(Asb[(r0+8)*AG_ASTRIDE + ks + tig + 4]);
                #pragma unroll
                for (int na = 0; na < 4; na++)
                    mma_tf32(c[ma][na], a, b[na]);
            }
        }
        if (kt + AG_STAGES - 1 < 64)
            ag_issue(asBase, bsBase, Abase, Bbase, r, q, (kt + AG_STAGES - 1) & 3,
                     kt + AG_STAGES - 1);
    }

    const int d  = db >> 3;
    const int bb = db & 7;
    #pragma unroll
    for (int ma = 0; ma < 2; ma++) {
        #pragma unroll
        for (int na = 0; na < 4; na++) {
            int n0 = mt*64 + wm + ma*16 + group;
            int o  = wn + na*8 + tig*2;
            size_t base = ((size_t)(d*1024 + n0)*8 + bb)*128 + o;
            *(float2*)&agg[base]        = make_float2(c[ma][na][0], c[ma][na][1]);
            *(float2*)&agg[base + 8192] = make_float2(c[ma][na][2], c[ma][na][3]);
        }
    }
}

// ---------------- support transpose: [d][n][b][o] -> [db][o][n], tf32-rounded ----------------
__global__ void transpose_support(const float* __restrict__ sup, float* __restrict__ supT)
{
    __shared__ float t[32][33];
    int db = blockIdx.z;
    int n0 = blockIdx.x * 32, o0 = blockIdx.y * 32;
    int d = db >> 3, b = db & 7;
    int tx = threadIdx.x, ty = threadIdx.y;   // 32 x 8
    #pragma unroll
    for (int j = 0; j < 4; j++) {
        int n = n0 + ty + j*8;
        t[ty + j*8][tx] = sup[((size_t)(d*1024 + n)*8 + b)*128 + o0 + tx];
    }
    __syncthreads();
    #pragma unroll
    for (int j = 0; j < 4; j++) {
        int o = o0 + ty + j*8;
        supT[((size_t)db*128 + o)*1024 + n0 + tx] = tf32f(t[tx][ty + j*8]);
    }
}

// ---------------- one-time weight prep ----------------
__global__ void prep_weights(const float* __restrict__ W,   const float* __restrict__ Whh,
                             const float* __restrict__ Wh,  const float* __restrict__ Wih,
                             const float* __restrict__ bhh, const float* __restrict__ Bh,
                             float* __restrict__ wT, float* __restrict__ whcat,
                             float* __restrict__ wihr, float* __restrict__ bcat)
{
    int idx = blockIdx.x*blockDim.x + threadIdx.x;   // < 131072
    if (idx < 2*DDIR*128*128) {                      // wT[l][d][o][f] = W[l][d][f][o] (raw)
        int ld = idx / 16384;
        int rem = idx & 16383;
        int o = rem >> 7, f = rem & 127;
        wT[idx] = W[((long)ld*128 + f)*128 + o];
    }
    if (idx < 2*512*128) {                           // whcat[l][n][k] (raw)
        int l = idx >> 16;
        int rem = idx & 65535;
        int n = rem >> 7, k = rem & 127;
        whcat[idx] = (n < 384) ? Whh[((long)l*384 + n)*128 + k]
                               : Wh[((long)l*128 + k)*128 + (n - 384)];
    }
    if (idx < 2*384*128) {                           // wihr = tf32(Wih), native layout
        wihr[idx] = tf32f(Wih[idx]);
    }
    if (idx < 2*512) {
        int l = idx >> 9, j = idx & 511;
        bcat[idx] = (j < 384) ? bhh[l*384 + j] : Bh[l*128 + (j-384)];
    }
}

// ---------------- fused GRU gates + d-sum + relu + highway ----------------
__global__ void gru_highway(const float* __restrict__ xin, const float* __restrict__ ght,
                            const float* __restrict__ gi, float* __restrict__ xout)
{
    int idx = blockIdx.x*blockDim.x + threadIdx.x;
    int o = idx & 127;
    int r = idx >> 7;
    float h = xin[idx];
    const float* g = ght + (long)r*512;
    float ghr = g[o], ghz = g[128+o], ghn = g[256+o];
    float t = fmaxf(g[384+o], 0.0f);
    float acc = 0.0f;
    #pragma unroll
    for (int d = 0; d < 3; d++) {
        const float* gp = gi + ((long)(d*8192 + r))*384;
        float rr = sigmoidf_(gp[o]       + ghr);
        float zz = sigmoidf_(gp[128 + o] + ghz);
        float nn = tanhf    (gp[256 + o] + rr*ghn);
        acc += (1.0f - zz)*nn + zz*h;
    }
    float outv = fmaxf(acc, 0.0f);
    xout[idx] = outv*t + h*(1.0f - t);
}

// ---------------------------------------------------------------------------
extern "C" void kernel_launch(void* const* d_in, const int* in_sizes, int n_in,
                              void* d_out, int out_size)
{
    const float* inputs = (const float*)d_in[0];
    const float* adj    = (const float*)d_in[1];
    const float* W      = (const float*)d_in[2];
    const float* Bc     = (const float*)d_in[3];
    const float* Wh     = (const float*)d_in[4];
    const float* Bh     = (const float*)d_in[5];
    const float* Wih    = (const float*)d_in[6];
    const float* Whh    = (const float*)d_in[7];
    const float* bih    = (const float*)d_in[8];
    const float* bhh    = (const float*)d_in[9];
    float* out = (float*)d_out;
    (void)in_sizes; (void)n_in; (void)out_size;

    float *support, *supT, *agg, *gi, *ght, *xmid, *wT, *whcat, *wihr, *bcat;
    cudaGetSymbolAddress((void**)&support, g_support);
    cudaGetSymbolAddress((void**)&supT,    g_supT);
    cudaGetSymbolAddress((void**)&agg,     g_agg);
    cudaGetSymbolAddress((void**)&gi,      g_gi);
    cudaGetSymbolAddress((void**)&ght,     g_ght);
    cudaGetSymbolAddress((void**)&xmid,    g_x);
    cudaGetSymbolAddress((void**)&wT,      g_wT);
    cudaGetSymbolAddress((void**)&whcat,   g_whcat);
    cudaGetSymbolAddress((void**)&wihr,    g_wihr);
    cudaGetSymbolAddress((void**)&bcat,    g_bcat);

    cudaFuncSetAttribute(agg_mma_k, cudaFuncAttributeMaxDynamicSharedMemorySize,
                         AG_SMEM_BYTES);

    prep_weights<<<512, 256>>>(W, Whh, Wh, Wih, bhh, Bh, wT, whcat, wihr, bcat);

    for (int l = 0; l < 2; l++) {
        const float* xi = (l == 0) ? inputs : xmid;
        float*       xo = (l == 1) ? out    : xmid;

        // support = x @ W^T + Bc   (3x exact, R8-proven config)
        mma_gemm_3x<<<dim3(64,1,3), 256>>>(
            xi, wT + (long)l*DDIR*16384, Bc + l*DDIR*128, support,
            128, 128, 128, 128,
            0L, 16384L, 1,
            (long)NNODES*BB*OO, 0L, 128);

        // supT = transpose, pre-rounded to tf32 (B operand of agg)
        transpose_support<<<dim3(32,4,24), dim3(32,8)>>>(support, supT);

        // agg = adj @ support   (1x tf32, cp.async pipeline)
        agg_mma_k<<<dim3(16,24), 256, AG_SMEM_BYTES>>>(adj, supT, agg);

        // gi = agg @ Wih^T + bih   (1x: B pre-rounded, A rounded at frag)
        mma_gemm_1x<<<dim3(192,3,1), 256>>>(
            agg, wihr + (long)l*384*128, bih + l*384, gi,
            128, 128, 128, 384,
            0L, 0L, 1, 0L, 0L, 0);

        // ght = x @ [Whh | Wh^T]^T + [bhh | Bh]   (3x exact, R8-proven config)
        mma_gemm_3x<<<dim3(64,4,1), 256>>>(
            xi, whcat + (long)l*512*128, bcat + l*512, ght,
            128, 128, 128, 512,
            0L, 0L, 1, 0L, 0L, 0);

        gru_highway<<<4096, 256>>>(xi, ght, gi, xo);
    }
}